// round 8
// baseline (speedup 1.0000x reference)
#include <cuda_runtime.h>

// LiveniumJoint closed form: h stays in span{h0, a0n, a1n, a2n}.
// R8 = R4 consumer (24-LDG reg burst, lane-parked single chain, output from
// h regs) + anchors in smem with k-outer amortized LDS (frees 72 regs ->
// 3 blocks/SM = 12 warps) + in-kernel anchor prep + persistent grid.

#define DD 768
#define VV 192            // float4 per row
#define KPL 6             // float4 per lane (192/32)
#define RB 4              // rows per warp-batch (one chain per batch)
#define FULLMASK 0xffffffffu

__device__ __forceinline__ float rcpa(float x) {
    float y; asm("rcp.approx.ftz.f32 %0,%1;" : "=f"(y) : "f"(x)); return y;
}
__device__ __forceinline__ float rsqa(float x) {
    float y; asm("rsqrt.approx.ftz.f32 %0,%1;" : "=f"(y) : "f"(x)); return y;
}
__device__ __forceinline__ float ex2a(float x) {
    float y; asm("ex2.approx.ftz.f32 %0,%1;" : "=f"(y) : "f"(x)); return y;
}

__global__ __launch_bounds__(128, 3)
void liv_fused(const float* __restrict__ h0,
               const float* __restrict__ anchors,
               float* __restrict__ out_h,
               float* __restrict__ out_al,
               int B) {
    __shared__ float4 s_an4[3 * VV];   // 9 KB normalized anchors
    __shared__ float  s_G[6];

    const int tid = threadIdx.x, wid = tid >> 5, lane = tid & 31;
    float* s_an = (float*)s_an4;

    // ---- in-block anchor prep (redundant per block, overlapped) ----
    if (wid < 3) {
        float acc = 0.f;
        for (int k = lane; k < DD; k += 32) {
            float x = anchors[wid * DD + k];
            acc = fmaf(x, x, acc);
        }
        #pragma unroll
        for (int o = 16; o; o >>= 1) acc += __shfl_xor_sync(FULLMASK, acc, o);
        float inv = 1.f / fmaxf(sqrtf(acc), 1e-12f);
        for (int k = lane; k < DD; k += 32)
            s_an[wid * DD + k] = anchors[wid * DD + k] * inv;
    }
    __syncthreads();
    if (wid == 0) {
        float d00 = 0, d01 = 0, d02 = 0, d11 = 0, d12 = 0, d22 = 0;
        for (int k = lane; k < DD; k += 32) {
            float x0 = s_an[k], x1 = s_an[DD + k], x2 = s_an[2 * DD + k];
            d00 = fmaf(x0, x0, d00); d01 = fmaf(x0, x1, d01); d02 = fmaf(x0, x2, d02);
            d11 = fmaf(x1, x1, d11); d12 = fmaf(x1, x2, d12); d22 = fmaf(x2, x2, d22);
        }
        #pragma unroll
        for (int o = 16; o; o >>= 1) {
            d00 += __shfl_xor_sync(FULLMASK, d00, o);
            d01 += __shfl_xor_sync(FULLMASK, d01, o);
            d02 += __shfl_xor_sync(FULLMASK, d02, o);
            d11 += __shfl_xor_sync(FULLMASK, d11, o);
            d12 += __shfl_xor_sync(FULLMASK, d12, o);
            d22 += __shfl_xor_sync(FULLMASK, d22, o);
        }
        if (lane == 0) {
            s_G[0] = d00; s_G[1] = d01; s_G[2] = d02;
            s_G[3] = d11; s_G[4] = d12; s_G[5] = d22;
        }
    }
    __syncthreads();

    const float G00 = s_G[0], G01 = s_G[1], G02 = s_G[2];
    const float G11 = s_G[3], G12 = s_G[4], G22 = s_G[5];

    const float4* A0 = s_an4;
    const float4* A1 = s_an4 + VV;
    const float4* A2 = s_an4 + 2 * VV;

    const int gw = (blockIdx.x * blockDim.x + tid) >> 5;
    const int nwarps = (gridDim.x * blockDim.x) >> 5;
    const int nbatch = (B + RB - 1) / RB;

    for (int b = gw; b < nbatch; b += nwarps) {
        const int base = b * RB;

        // ---- burst: 24 LDG.128 in flight ----
        float4 h[RB][KPL];
        #pragma unroll
        for (int j = 0; j < RB; j++) {
            int row = base + j; if (row >= B) row = B - 1;
            const float4* hp = (const float4*)h0 + (size_t)row * VV;
            #pragma unroll
            for (int k = 0; k < KPL; k++) h[j][k] = __ldg(hp + k * 32 + lane);
        }

        // ---- k-outer dots: anchor LDS amortized over 4 rows ----
        float N[RB], T0[RB], T1[RB], T2[RB];
        #pragma unroll
        for (int j = 0; j < RB; j++) { N[j] = T0[j] = T1[j] = T2[j] = 0.f; }
        #pragma unroll
        for (int k = 0; k < KPL; k++) {
            const float4 a0 = A0[k * 32 + lane];
            const float4 a1 = A1[k * 32 + lane];
            const float4 a2 = A2[k * 32 + lane];
            #pragma unroll
            for (int j = 0; j < RB; j++) {
                const float4 v = h[j][k];
                N[j]  = fmaf(v.x, v.x, N[j]);
                N[j]  = fmaf(v.y, v.y, N[j]);
                N[j]  = fmaf(v.z, v.z, N[j]);
                N[j]  = fmaf(v.w, v.w, N[j]);
                T0[j] = fmaf(v.x, a0.x, T0[j]);
                T0[j] = fmaf(v.y, a0.y, T0[j]);
                T0[j] = fmaf(v.z, a0.z, T0[j]);
                T0[j] = fmaf(v.w, a0.w, T0[j]);
                T1[j] = fmaf(v.x, a1.x, T1[j]);
                T1[j] = fmaf(v.y, a1.y, T1[j]);
                T1[j] = fmaf(v.z, a1.z, T1[j]);
                T1[j] = fmaf(v.w, a1.w, T1[j]);
                T2[j] = fmaf(v.x, a2.x, T2[j]);
                T2[j] = fmaf(v.y, a2.y, T2[j]);
                T2[j] = fmaf(v.z, a2.z, T2[j]);
                T2[j] = fmaf(v.w, a2.w, T2[j]);
            }
        }

        // ---- reduce, park scalars in lane j ----
        float myN = 0.f, myT0 = 0.f, myT1 = 0.f, myT2 = 0.f;
        #pragma unroll
        for (int j = 0; j < RB; j++) {
            #pragma unroll
            for (int o = 16; o; o >>= 1) {
                N[j]  += __shfl_xor_sync(FULLMASK, N[j],  o);
                T0[j] += __shfl_xor_sync(FULLMASK, T0[j], o);
                T1[j] += __shfl_xor_sync(FULLMASK, T1[j], o);
                T2[j] += __shfl_xor_sync(FULLMASK, T2[j], o);
            }
            if (lane == j) { myN = N[j]; myT0 = T0[j]; myT1 = T1[j]; myT2 = T2[j]; }
        }

        // ---- ONE branchless chain: lane j computes row base+j ----
        float p = 1.f, q0 = 0.f, q1 = 0.f, q2 = 0.f;
        float al0 = 0.f, al1 = 0.f, al2 = 0.f;
        const float KK = 28.853900817779268f;  // 20 * log2(e)
        #pragma unroll
        for (int s = 0; s < 7; s++) {
            float s0 = fmaf(p, myT0, fmaf(q0, G00, fmaf(q1, G01, q2 * G02)));
            float s1 = fmaf(p, myT1, fmaf(q0, G01, fmaf(q1, G11, q2 * G12)));
            float s2 = fmaf(p, myT2, fmaf(q0, G02, fmaf(q1, G12, q2 * G22)));
            float qT = fmaf(q0, myT0, fmaf(q1, myT1, q2 * myT2));
            float n2 = fmaf(p, fmaf(p, myN, qT),
                            fmaf(q0, s0, fmaf(q1, s1, q2 * s2)));
            float inv = rsqa(fmaxf(n2, 1e-24f));
            al0 = s0 * inv; al1 = s1 * inv; al2 = s2 * inv;
            if (s == 6) break;

            float e0 = ex2a(KK * al0);
            float e1 = ex2a(KK * al1);
            float e2 = ex2a(KK * al2);
            float invW = rcpa(e0 + e1 + e2);
            float w0 = e0 * invW, w1 = e1 * invW, w2 = e2 * invW;

            float c = fmaf(w0, al0, fmaf(w1, al1, w2 * al2));
            float beta = fmaf(-0.05f, c, 1.f);
            float n = n2 * inv;            // sqrt(n2)
            float delta = 0.05f * n;
            p *= beta;
            q0 = fmaf(beta, q0, delta * w0);
            q1 = fmaf(beta, q1, delta * w1);
            q2 = fmaf(beta, q2, delta * w2);

            float t2 = fmaf(w0 * w0, G00,
                       fmaf(w1 * w1, G11,
                       fmaf(w2 * w2, G22,
                       2.f * fmaf(w0 * w1, G01,
                             fmaf(w0 * w2, G02, w1 * w2 * G12)))));
            float n2b = n2 * fmaf(0.0025f, t2 - c * c, 1.f);
            float g = fminf(1.f, 10.f * rsqa(n2b));
            p *= g; q0 *= g; q1 *= g; q2 *= g;
        }

        // ---- outputs: k-outer, h from regs, anchors from smem ----
        float pj[RB], q0j[RB], q1j[RB], q2j[RB];
        #pragma unroll
        for (int j = 0; j < RB; j++) {
            pj[j]  = __shfl_sync(FULLMASK, p,  j);
            q0j[j] = __shfl_sync(FULLMASK, q0, j);
            q1j[j] = __shfl_sync(FULLMASK, q1, j);
            q2j[j] = __shfl_sync(FULLMASK, q2, j);
        }
        #pragma unroll
        for (int k = 0; k < KPL; k++) {
            const float4 a0 = A0[k * 32 + lane];
            const float4 a1 = A1[k * 32 + lane];
            const float4 a2 = A2[k * 32 + lane];
            #pragma unroll
            for (int j = 0; j < RB; j++) {
                const int row = base + j;
                if (row < B) {
                    const float4 v = h[j][k];
                    float4 o;
                    o.x = fmaf(pj[j], v.x, fmaf(q0j[j], a0.x, fmaf(q1j[j], a1.x, q2j[j] * a2.x)));
                    o.y = fmaf(pj[j], v.y, fmaf(q0j[j], a0.y, fmaf(q1j[j], a1.y, q2j[j] * a2.y)));
                    o.z = fmaf(pj[j], v.z, fmaf(q0j[j], a0.z, fmaf(q1j[j], a1.z, q2j[j] * a2.z)));
                    o.w = fmaf(pj[j], v.w, fmaf(q0j[j], a0.w, fmaf(q1j[j], a1.w, q2j[j] * a2.w)));
                    ((float4*)out_h)[(size_t)row * VV + k * 32 + lane] = o;
                }
            }
        }
        if (lane < RB && base + lane < B) {
            float* ap = out_al + (size_t)(base + lane) * 3;
            ap[0] = al0; ap[1] = al1; ap[2] = al2;
        }
    }
}

// ---------------------------------------------------------------------------
extern "C" void kernel_launch(void* const* d_in, const int* in_sizes, int n_in,
                              void* d_out, int out_size) {
    const float* h0 = (const float*)d_in[0];       // [B, 768]
    const float* anchors = (const float*)d_in[1];  // [3, 768]
    const int B = in_sizes[0] / DD;

    float* out_h = (float*)d_out;                    // [B, 768]
    float* out_al = (float*)d_out + (size_t)B * DD;  // [B, 3]

    const int threads = 128;              // 4 warps/block
    int nbatch = (B + RB - 1) / RB;       // 16384
    int blocks = 444;                     // 3 blocks/SM x 148 SMs, persistent
    int total_warps = blocks * (threads / 32);
    if (total_warps > nbatch) blocks = (nbatch + 3) / 4;
    liv_fused<<<blocks, threads>>>(h0, anchors, out_h, out_al, B);
}

// round 9
// speedup vs baseline: 1.3500x; 1.3500x over previous
#include <cuda_runtime.h>

// LiveniumJoint closed form: h stays in span{h0, a0n, a1n, a2n}.
// R9 = R4 exactly (reg anchors, j-outer 24-LDG burst, lane-parked single
// chain, output from h regs) + per-warp in-register anchor prep (no second
// kernel) + L2 prefetch of the next batch during the scalar chain.

#define DD 768
#define VV 192            // float4 per row
#define KPL 6             // float4 per lane (192/32)
#define RB 4              // rows per warp-batch
#define FULLMASK 0xffffffffu

__device__ __forceinline__ float rcpa(float x) {
    float y; asm("rcp.approx.ftz.f32 %0,%1;" : "=f"(y) : "f"(x)); return y;
}
__device__ __forceinline__ float rsqa(float x) {
    float y; asm("rsqrt.approx.ftz.f32 %0,%1;" : "=f"(y) : "f"(x)); return y;
}
__device__ __forceinline__ float ex2a(float x) {
    float y; asm("ex2.approx.ftz.f32 %0,%1;" : "=f"(y) : "f"(x)); return y;
}
__device__ __forceinline__ void pfL2(const void* p) {
    asm volatile("prefetch.global.L2 [%0];" :: "l"(p));
}

__global__ void liv_fused(const float* __restrict__ h0,
                          const float* __restrict__ anchors,
                          float* __restrict__ out_h,
                          float* __restrict__ out_al,
                          int B) {
    const int tid = threadIdx.x, lane = tid & 31;

    // ---- per-warp anchor prep, all in registers (anchors L2-hot) ----
    float4 A0[KPL], A1[KPL], A2[KPL];
    {
        const float4* av = (const float4*)anchors;
        #pragma unroll
        for (int k = 0; k < KPL; k++) {
            A0[k] = __ldg(av + k * 32 + lane);
            A1[k] = __ldg(av + VV + k * 32 + lane);
            A2[k] = __ldg(av + 2 * VV + k * 32 + lane);
        }
    }
    float n0 = 0.f, n1 = 0.f, n2 = 0.f, d01 = 0.f, d02 = 0.f, d12 = 0.f;
    #pragma unroll
    for (int k = 0; k < KPL; k++) {
        n0 = fmaf(A0[k].x, A0[k].x, n0); n0 = fmaf(A0[k].y, A0[k].y, n0);
        n0 = fmaf(A0[k].z, A0[k].z, n0); n0 = fmaf(A0[k].w, A0[k].w, n0);
        n1 = fmaf(A1[k].x, A1[k].x, n1); n1 = fmaf(A1[k].y, A1[k].y, n1);
        n1 = fmaf(A1[k].z, A1[k].z, n1); n1 = fmaf(A1[k].w, A1[k].w, n1);
        n2 = fmaf(A2[k].x, A2[k].x, n2); n2 = fmaf(A2[k].y, A2[k].y, n2);
        n2 = fmaf(A2[k].z, A2[k].z, n2); n2 = fmaf(A2[k].w, A2[k].w, n2);
        d01 = fmaf(A0[k].x, A1[k].x, d01); d01 = fmaf(A0[k].y, A1[k].y, d01);
        d01 = fmaf(A0[k].z, A1[k].z, d01); d01 = fmaf(A0[k].w, A1[k].w, d01);
        d02 = fmaf(A0[k].x, A2[k].x, d02); d02 = fmaf(A0[k].y, A2[k].y, d02);
        d02 = fmaf(A0[k].z, A2[k].z, d02); d02 = fmaf(A0[k].w, A2[k].w, d02);
        d12 = fmaf(A1[k].x, A2[k].x, d12); d12 = fmaf(A1[k].y, A2[k].y, d12);
        d12 = fmaf(A1[k].z, A2[k].z, d12); d12 = fmaf(A1[k].w, A2[k].w, d12);
    }
    #pragma unroll
    for (int o = 16; o; o >>= 1) {
        n0  += __shfl_xor_sync(FULLMASK, n0,  o);
        n1  += __shfl_xor_sync(FULLMASK, n1,  o);
        n2  += __shfl_xor_sync(FULLMASK, n2,  o);
        d01 += __shfl_xor_sync(FULLMASK, d01, o);
        d02 += __shfl_xor_sync(FULLMASK, d02, o);
        d12 += __shfl_xor_sync(FULLMASK, d12, o);
    }
    // normalize register anchors; form Gram of normalized anchors
    const float i0 = 1.f / fmaxf(sqrtf(n0), 1e-12f);
    const float i1 = 1.f / fmaxf(sqrtf(n1), 1e-12f);
    const float i2 = 1.f / fmaxf(sqrtf(n2), 1e-12f);
    #pragma unroll
    for (int k = 0; k < KPL; k++) {
        A0[k].x *= i0; A0[k].y *= i0; A0[k].z *= i0; A0[k].w *= i0;
        A1[k].x *= i1; A1[k].y *= i1; A1[k].z *= i1; A1[k].w *= i1;
        A2[k].x *= i2; A2[k].y *= i2; A2[k].z *= i2; A2[k].w *= i2;
    }
    const float G00 = n0 * i0 * i0, G11 = n1 * i1 * i1, G22 = n2 * i2 * i2;
    const float G01 = d01 * i0 * i1, G02 = d02 * i0 * i2, G12 = d12 * i1 * i2;

    const int gw = (blockIdx.x * blockDim.x + tid) >> 5;
    const int nwarps = (gridDim.x * blockDim.x) >> 5;
    const int nbatch = (B + RB - 1) / RB;
    const float4* hp = (const float4*)h0;

    for (int b = gw; b < nbatch; b += nwarps) {
        const int base = b * RB;

        // ---- burst: 24 LDG.128 in flight ----
        float4 h[RB][KPL];
        #pragma unroll
        for (int j = 0; j < RB; j++) {
            int row = base + j; if (row >= B) row = B - 1;
            const float4* rp = hp + (size_t)row * VV;
            #pragma unroll
            for (int k = 0; k < KPL; k++) h[j][k] = __ldg(rp + k * 32 + lane);
        }

        // ---- L2-prefetch next batch (96 lines, 3 warp instructions) ----
        {
            const int nb = b + nwarps;
            if (nb < nbatch) {
                const size_t nbase = (size_t)nb * RB;
                #pragma unroll
                for (int t = 0; t < 3; t++) {
                    int f = t * 32 + lane;            // 0..95
                    int r = f / 24, lc = f - r * 24;  // row, 128B line
                    const char* a = (const char*)(hp + (nbase + r) * VV) + lc * 128;
                    pfL2(a);
                }
            }
        }

        // ---- per-row dots + reduce; park scalars in lane j ----
        float myN = 0.f, myT0 = 0.f, myT1 = 0.f, myT2 = 0.f;
        #pragma unroll
        for (int j = 0; j < RB; j++) {
            float N0 = 0.f, T0 = 0.f, T1 = 0.f, T2 = 0.f;
            #pragma unroll
            for (int k = 0; k < KPL; k++) {
                const float4 v = h[j][k];
                N0 = fmaf(v.x, v.x, N0);
                N0 = fmaf(v.y, v.y, N0);
                N0 = fmaf(v.z, v.z, N0);
                N0 = fmaf(v.w, v.w, N0);
                T0 = fmaf(v.x, A0[k].x, T0);
                T0 = fmaf(v.y, A0[k].y, T0);
                T0 = fmaf(v.z, A0[k].z, T0);
                T0 = fmaf(v.w, A0[k].w, T0);
                T1 = fmaf(v.x, A1[k].x, T1);
                T1 = fmaf(v.y, A1[k].y, T1);
                T1 = fmaf(v.z, A1[k].z, T1);
                T1 = fmaf(v.w, A1[k].w, T1);
                T2 = fmaf(v.x, A2[k].x, T2);
                T2 = fmaf(v.y, A2[k].y, T2);
                T2 = fmaf(v.z, A2[k].z, T2);
                T2 = fmaf(v.w, A2[k].w, T2);
            }
            #pragma unroll
            for (int o = 16; o; o >>= 1) {
                N0 += __shfl_xor_sync(FULLMASK, N0, o);
                T0 += __shfl_xor_sync(FULLMASK, T0, o);
                T1 += __shfl_xor_sync(FULLMASK, T1, o);
                T2 += __shfl_xor_sync(FULLMASK, T2, o);
            }
            if (lane == j) { myN = N0; myT0 = T0; myT1 = T1; myT2 = T2; }
        }

        // ---- ONE branchless chain: lane j computes row base+j ----
        float p = 1.f, q0 = 0.f, q1 = 0.f, q2 = 0.f;
        float al0 = 0.f, al1 = 0.f, al2 = 0.f;
        const float KK = 28.853900817779268f;  // 20 * log2(e)
        #pragma unroll
        for (int s = 0; s < 7; s++) {
            float s0 = fmaf(p, myT0, fmaf(q0, G00, fmaf(q1, G01, q2 * G02)));
            float s1 = fmaf(p, myT1, fmaf(q0, G01, fmaf(q1, G11, q2 * G12)));
            float s2 = fmaf(p, myT2, fmaf(q0, G02, fmaf(q1, G12, q2 * G22)));
            float qT = fmaf(q0, myT0, fmaf(q1, myT1, q2 * myT2));
            float n2r = fmaf(p, fmaf(p, myN, qT),
                             fmaf(q0, s0, fmaf(q1, s1, q2 * s2)));
            float inv = rsqa(fmaxf(n2r, 1e-24f));
            al0 = s0 * inv; al1 = s1 * inv; al2 = s2 * inv;
            if (s == 6) break;

            float e0 = ex2a(KK * al0);
            float e1 = ex2a(KK * al1);
            float e2 = ex2a(KK * al2);
            float invW = rcpa(e0 + e1 + e2);
            float w0 = e0 * invW, w1 = e1 * invW, w2 = e2 * invW;

            float c = fmaf(w0, al0, fmaf(w1, al1, w2 * al2));
            float beta = fmaf(-0.05f, c, 1.f);
            float n = n2r * inv;            // sqrt(n2)
            float delta = 0.05f * n;
            p *= beta;
            q0 = fmaf(beta, q0, delta * w0);
            q1 = fmaf(beta, q1, delta * w1);
            q2 = fmaf(beta, q2, delta * w2);

            float t2 = fmaf(w0 * w0, G00,
                       fmaf(w1 * w1, G11,
                       fmaf(w2 * w2, G22,
                       2.f * fmaf(w0 * w1, G01,
                             fmaf(w0 * w2, G02, w1 * w2 * G12)))));
            float n2b = n2r * fmaf(0.0025f, t2 - c * c, 1.f);
            float g = fminf(1.f, 10.f * rsqa(n2b));
            p *= g; q0 *= g; q1 *= g; q2 *= g;
        }

        // ---- outputs: broadcast (p,q) from lane j, h from regs ----
        #pragma unroll
        for (int j = 0; j < RB; j++) {
            const int row = base + j;
            const float pj  = __shfl_sync(FULLMASK, p,  j);
            const float q0j = __shfl_sync(FULLMASK, q0, j);
            const float q1j = __shfl_sync(FULLMASK, q1, j);
            const float q2j = __shfl_sync(FULLMASK, q2, j);
            if (row < B) {
                float4* op = (float4*)out_h + (size_t)row * VV;
                #pragma unroll
                for (int k = 0; k < KPL; k++) {
                    float4 o;
                    o.x = fmaf(pj, h[j][k].x, fmaf(q0j, A0[k].x, fmaf(q1j, A1[k].x, q2j * A2[k].x)));
                    o.y = fmaf(pj, h[j][k].y, fmaf(q0j, A0[k].y, fmaf(q1j, A1[k].y, q2j * A2[k].y)));
                    o.z = fmaf(pj, h[j][k].z, fmaf(q0j, A0[k].z, fmaf(q1j, A1[k].z, q2j * A2[k].z)));
                    o.w = fmaf(pj, h[j][k].w, fmaf(q0j, A0[k].w, fmaf(q1j, A1[k].w, q2j * A2[k].w)));
                    op[k * 32 + lane] = o;
                }
            }
        }
        if (lane < RB && base + lane < B) {
            float* ap = out_al + (size_t)(base + lane) * 3;
            ap[0] = al0; ap[1] = al1; ap[2] = al2;
        }
    }
}

// ---------------------------------------------------------------------------
extern "C" void kernel_launch(void* const* d_in, const int* in_sizes, int n_in,
                              void* d_out, int out_size) {
    const float* h0 = (const float*)d_in[0];       // [B, 768]
    const float* anchors = (const float*)d_in[1];  // [3, 768]
    const int B = in_sizes[0] / DD;

    float* out_h = (float*)d_out;                    // [B, 768]
    float* out_al = (float*)d_out + (size_t)B * DD;  // [B, 3]

    const int threads = 128;              // 4 warps/block
    int nbatch = (B + RB - 1) / RB;       // 16384 batches of 4 rows
    int blocks = 1024;                    // 4096 warps -> 4 batches each
    int total_warps = blocks * (threads / 32);
    if (total_warps > nbatch) blocks = (nbatch + 3) / 4;
    liv_fused<<<blocks, threads>>>(h0, anchors, out_h, out_al, B);
}